// round 1
// baseline (speedup 1.0000x reference)
#include <cuda_runtime.h>
#include <cuda_bf16.h>

#define NU 100000
#define NI 50000
#define NE 200000
#define NR 64
#define D 64
#define KNB 16
#define EDGES 2000000
#define LAYERS 2
#define BB 4096
#define REG 0.0001f

// ---------------- scratch (no alloc allowed -> __device__ globals) ----------
__device__ float g_aggu0[NU * D];
__device__ float g_aggu1[NU * D];
__device__ float g_aggi0[NI * D];
__device__ float g_aggi1[NI * D];
__device__ float g_kg[NI * D];
__device__ float g_ic1[NI * D];
__device__ float g_ic2[NI * D];
__device__ float g_rw[LAYERS * NR * D];
__device__ float g_rb[LAYERS * NR];
__device__ float g_acc;

// ---------------- precompute rw[l,rel,d] = sum_o r_o * (Wk[:, :D]+Wk[:, D:])[o,d]
__global__ void k_rw(const float* __restrict__ remb,
                     const float* __restrict__ Wk_w,
                     const float* __restrict__ Wk_b,
                     float* __restrict__ rw, float* __restrict__ rb,
                     float* __restrict__ acc) {
    int l = blockIdx.x >> 6;
    int rr = blockIdx.x & 63;
    int d = threadIdx.x;
    const float* W = Wk_w + (size_t)l * D * 2 * D;
    const float* re = remb + rr * D;
    float a = 0.f;
#pragma unroll 8
    for (int o = 0; o < D; o++)
        a += re[o] * (W[o * 2 * D + d] + W[o * 2 * D + D + d]);
    rw[(l * NR + rr) * D + d] = a;
    if (d == 0) {
        const float* b = Wk_b + l * D;
        float s = 0.f;
        for (int o = 0; o < D; o++) s += re[o] * b[o];
        rb[l * NR + rr] = s;
    }
    if (blockIdx.x == 0 && d == 0) *acc = 0.f;
}

// ---------------- KG attention: one warp per item --------------------------
__global__ void k_attn(const float* __restrict__ icur,
                       const float* __restrict__ eemb,
                       const int* __restrict__ kg_ent,
                       const int* __restrict__ kg_rel,
                       const float* __restrict__ rw,
                       const float* __restrict__ rb,
                       float* __restrict__ kg_out) {
    __shared__ float s_rw[NR * D];
    __shared__ float s_rb[NR];
    int tid = threadIdx.x;
    for (int i = tid; i < NR * D; i += 256) s_rw[i] = rw[i];
    if (tid < NR) s_rb[tid] = rb[tid];
    __syncthreads();

    int warp = tid >> 5, lane = tid & 31;
    int item = blockIdx.x * 8 + warp;
    if (item >= NI) return;

    float2 ic = *(const float2*)(icur + (size_t)item * D + lane * 2);
    float2 v[KNB];
    float sc[KNB];
    int base = item * KNB;
#pragma unroll
    for (int k = 0; k < KNB; k++) {
        int e = kg_ent[base + k];
        int rr = kg_rel[base + k];
        v[k] = *(const float2*)(eemb + (size_t)e * D + lane * 2);
        float2 w = *(const float2*)(s_rw + rr * D + lane * 2);
        float p = v[k].x * ic.x * w.x + v[k].y * ic.y * w.y;
#pragma unroll
        for (int off = 16; off; off >>= 1) p += __shfl_xor_sync(0xffffffffu, p, off);
        p += s_rb[rr];
        sc[k] = p >= 0.f ? p : 0.2f * p;
    }
    float m = sc[0];
#pragma unroll
    for (int k = 1; k < KNB; k++) m = fmaxf(m, sc[k]);
    float s = 0.f;
#pragma unroll
    for (int k = 0; k < KNB; k++) { sc[k] = __expf(sc[k] - m); s += sc[k]; }
    float inv = 1.f / s;
    float ax = 0.f, ay = 0.f;
#pragma unroll
    for (int k = 0; k < KNB; k++) {
        float a = sc[k] * inv;
        ax += a * v[k].x;
        ay += a * v[k].y;
    }
    float2 o;
    o.x = ax; o.y = ay;
    *(float2*)(kg_out + (size_t)item * D + lane * 2) = o;
}

// ---------------- edge scatter: one warp per edge ---------------------------
// lanes 0-15 : agg_i[i] += nrm * u_cur[u]   (4 floats each, red.v4)
// lanes 16-31: agg_u[u] += nrm * i_cur[i]
__global__ void k_scatter(const float* __restrict__ ucur,
                          const float* __restrict__ icur,
                          const int* __restrict__ eu,
                          const int* __restrict__ ei,
                          const float* __restrict__ enorm,
                          float* __restrict__ aggu,
                          float* __restrict__ aggi) {
    int e = (blockIdx.x * blockDim.x + threadIdx.x) >> 5;
    int lane = threadIdx.x & 31;
    if (e >= EDGES) return;
    int u = eu[e];
    int i = ei[e];
    float nrm = enorm[e];
    int part = lane >> 4;
    int j = (lane & 15) * 4;
    const float* src = part ? icur + (size_t)i * D + j : ucur + (size_t)u * D + j;
    float* dst = part ? aggu + (size_t)u * D + j : aggi + (size_t)i * D + j;
    float4 s = *(const float4*)src;
    asm volatile("red.global.add.v4.f32 [%0], {%1,%2,%3,%4};"
                 :: "l"(dst), "f"(nrm * s.x), "f"(nrm * s.y),
                    "f"(nrm * s.z), "f"(nrm * s.w)
                 : "memory");
}

// ---------------- gate + item update: one warp per item ---------------------
__global__ void k_gate(const float* __restrict__ kg,
                       const float* __restrict__ aggi,
                       const float* __restrict__ Wa_w,
                       const float* __restrict__ Wa_b,
                       const float* __restrict__ Wb_w,
                       const float* __restrict__ Wb_b,
                       float* __restrict__ inew) {
    __shared__ float sWa[D * 65];
    __shared__ float sWb[D * 65];
    __shared__ float sba[D], sbb[D];
    __shared__ float skg[8][D], sag[8][D];
    int tid = threadIdx.x;
    for (int i = tid; i < D * D; i += 256) {
        int o = i >> 6, d = i & 63;
        sWa[o * 65 + d] = Wa_w[i];
        sWb[o * 65 + d] = Wb_w[i];
    }
    if (tid < D) { sba[tid] = Wa_b[tid]; sbb[tid] = Wb_b[tid]; }
    __syncthreads();

    int warp = tid >> 5, lane = tid & 31;
    int item = blockIdx.x * 8 + warp;
    if (item >= NI) return;

    float2 kv = *(const float2*)(kg + (size_t)item * D + lane * 2);
    float2 av = *(const float2*)(aggi + (size_t)item * D + lane * 2);
    skg[warp][lane * 2] = kv.x; skg[warp][lane * 2 + 1] = kv.y;
    sag[warp][lane * 2] = av.x; sag[warp][lane * 2 + 1] = av.y;
    __syncwarp();

    float g[2];
#pragma unroll
    for (int t = 0; t < 2; t++) {
        int o = lane * 2 + t;
        float acc = sba[o] + sbb[o];
        const float* wa = sWa + o * 65;
        const float* wb = sWb + o * 65;
#pragma unroll 16
        for (int d = 0; d < D; d++)
            acc += skg[warp][d] * wa[d] + sag[warp][d] * wb[d];
        g[t] = 1.f / (1.f + __expf(-acc));
    }
    float2 o2;
    o2.x = g[0] * kv.x + (1.f - g[0]) * av.x;
    o2.y = g[1] * kv.y + (1.f - g[1]) * av.y;
    *(float2*)(inew + (size_t)item * D + lane * 2) = o2;
}

// ---------------- loss: one warp per batch element --------------------------
__global__ void k_loss(const float* __restrict__ uemb,
                       const float* __restrict__ aggu0,
                       const float* __restrict__ aggu1,
                       const float* __restrict__ iemb,
                       const float* __restrict__ ic1,
                       const float* __restrict__ ic2,
                       const int* __restrict__ user,
                       const int* __restrict__ pos,
                       const int* __restrict__ neg,
                       float* __restrict__ acc) {
    int b = (blockIdx.x * blockDim.x + threadIdx.x) >> 5;
    int lane = threadIdx.x & 31;
    if (b >= BB) return;
    size_t u = (size_t)user[b] * D;
    size_t p = (size_t)pos[b] * D;
    size_t n = (size_t)neg[b] * D;

    float ps = 0.f, ns = 0.f, l2 = 0.f;
    int d = lane * 2;
    float2 ua = *(const float2*)(uemb + u + d);
    float2 ub = *(const float2*)(aggu0 + u + d);
    float2 uc = *(const float2*)(aggu1 + u + d);
    float2 pa = *(const float2*)(iemb + p + d);
    float2 pb = *(const float2*)(ic1 + p + d);
    float2 pc = *(const float2*)(ic2 + p + d);
    float2 na = *(const float2*)(iemb + n + d);
    float2 nb = *(const float2*)(ic1 + n + d);
    float2 nc = *(const float2*)(ic2 + n + d);
    float uex = ua.x + ub.x + uc.x, uey = ua.y + ub.y + uc.y;
    float pex = pa.x + pb.x + pc.x, pey = pa.y + pb.y + pc.y;
    float nex = na.x + nb.x + nc.x, ney = na.y + nb.y + nc.y;
    ps = uex * pex + uey * pey;
    ns = uex * nex + uey * ney;
    l2 = uex * uex + uey * uey + pex * pex + pey * pey + nex * nex + ney * ney;
#pragma unroll
    for (int off = 16; off; off >>= 1) {
        ps += __shfl_xor_sync(0xffffffffu, ps, off);
        ns += __shfl_xor_sync(0xffffffffu, ns, off);
        l2 += __shfl_xor_sync(0xffffffffu, l2, off);
    }
    if (lane == 0) {
        float x = ps - ns;
        float sg = 1.f / (1.f + expf(-x));
        float term = -logf(sg + 1e-10f) + REG * l2;
        atomicAdd(acc, term);
    }
}

__global__ void k_final(const float* __restrict__ acc, float* __restrict__ out) {
    out[0] = acc[0] * (1.f / (float)BB);
}

// ---------------- launch -----------------------------------------------------
extern "C" void kernel_launch(void* const* d_in, const int* in_sizes, int n_in,
                              void* d_out, int out_size) {
    const float* uemb  = (const float*)d_in[0];
    const float* iemb  = (const float*)d_in[1];
    const float* eemb  = (const float*)d_in[2];
    const float* remb  = (const float*)d_in[3];
    const float* Wk_w  = (const float*)d_in[4];
    const float* Wk_b  = (const float*)d_in[5];
    const float* Wa_w  = (const float*)d_in[6];
    const float* Wa_b  = (const float*)d_in[7];
    const float* Wb_w  = (const float*)d_in[8];
    const float* Wb_b  = (const float*)d_in[9];
    const float* enorm = (const float*)d_in[10];
    const int* user    = (const int*)d_in[11];
    const int* pos     = (const int*)d_in[12];
    const int* neg     = (const int*)d_in[13];
    const int* eu      = (const int*)d_in[14];
    const int* ei      = (const int*)d_in[15];
    const int* kg_rel  = (const int*)d_in[16];
    const int* kg_ent  = (const int*)d_in[17];

    float *aggu0, *aggu1, *aggi0, *aggi1, *kg, *ic1, *ic2, *rw, *rb, *acc;
    cudaGetSymbolAddress((void**)&aggu0, g_aggu0);
    cudaGetSymbolAddress((void**)&aggu1, g_aggu1);
    cudaGetSymbolAddress((void**)&aggi0, g_aggi0);
    cudaGetSymbolAddress((void**)&aggi1, g_aggi1);
    cudaGetSymbolAddress((void**)&kg, g_kg);
    cudaGetSymbolAddress((void**)&ic1, g_ic1);
    cudaGetSymbolAddress((void**)&ic2, g_ic2);
    cudaGetSymbolAddress((void**)&rw, g_rw);
    cudaGetSymbolAddress((void**)&rb, g_rb);
    cudaGetSymbolAddress((void**)&acc, g_acc);

    cudaMemsetAsync(aggu0, 0, sizeof(float) * NU * D);
    cudaMemsetAsync(aggu1, 0, sizeof(float) * NU * D);
    cudaMemsetAsync(aggi0, 0, sizeof(float) * NI * D);
    cudaMemsetAsync(aggi1, 0, sizeof(float) * NI * D);

    k_rw<<<LAYERS * NR, D>>>(remb, Wk_w, Wk_b, rw, rb, acc);

    // ---- layer 0 (u_cur = uemb, i_cur = iemb) ----
    k_attn<<<(NI + 7) / 8, 256>>>(iemb, eemb, kg_ent, kg_rel, rw, rb, kg);
    k_scatter<<<(EDGES * 32 + 255) / 256, 256>>>(uemb, iemb, eu, ei, enorm, aggu0, aggi0);
    k_gate<<<(NI + 7) / 8, 256>>>(kg, aggi0, Wa_w, Wa_b, Wb_w, Wb_b, ic1);

    // ---- layer 1 (u_cur = aggu0, i_cur = ic1) ----
    k_attn<<<(NI + 7) / 8, 256>>>(ic1, eemb, kg_ent, kg_rel, rw + NR * D, rb + NR, kg);
    k_scatter<<<(EDGES * 32 + 255) / 256, 256>>>(aggu0, ic1, eu, ei, enorm, aggu1, aggi1);
    k_gate<<<(NI + 7) / 8, 256>>>(kg, aggi1, Wa_w + D * D, Wa_b + D, Wb_w + D * D, Wb_b + D, ic2);

    // ---- loss ----
    k_loss<<<(BB * 32 + 255) / 256, 256>>>(uemb, aggu0, aggu1, iemb, ic1, ic2,
                                           user, pos, neg, acc);
    k_final<<<1, 1>>>(acc, (float*)d_out);
}

// round 2
// speedup vs baseline: 1.1631x; 1.1631x over previous
#include <cuda_runtime.h>
#include <cuda_bf16.h>

#define NU 100000
#define NI 50000
#define NE 200000
#define NR 64
#define D 64
#define KNB 16
#define EDGES 2000000
#define LAYERS 2
#define BB 4096
#define REG 0.0001f

// ---------------- scratch (no alloc allowed -> __device__ globals) ----------
// fused agg buffer so one memset clears everything that needs zeroing
__device__ float g_agg[(2 * NU + 2 * NI) * D];
__device__ float g_kg[NI * D];
__device__ float g_ic1[NI * D];
__device__ float g_ic2[NI * D];
__device__ float g_rw[LAYERS * NR * D];
__device__ float g_rb[LAYERS * NR];
__device__ float g_wat[LAYERS * D * D];   // Wa transposed [l][d][o]
__device__ float g_wbt[LAYERS * D * D];   // Wb transposed [l][d][o]
__device__ float g_bsum[LAYERS * D];      // Wa_b + Wb_b
__device__ float g_acc;

// ---------------- precompute rw[l,rel,d] = sum_o r_o * (Wk[:, :D]+Wk[:, D:])[o,d]
__global__ void k_rw(const float* __restrict__ remb,
                     const float* __restrict__ Wk_w,
                     const float* __restrict__ Wk_b,
                     float* __restrict__ rw, float* __restrict__ rb,
                     float* __restrict__ acc) {
    int l = blockIdx.x >> 6;
    int rr = blockIdx.x & 63;
    int d = threadIdx.x;
    const float* W = Wk_w + (size_t)l * D * 2 * D;
    const float* re = remb + rr * D;
    float a = 0.f;
#pragma unroll 8
    for (int o = 0; o < D; o++)
        a += re[o] * (W[o * 2 * D + d] + W[o * 2 * D + D + d]);
    rw[(l * NR + rr) * D + d] = a;
    if (d == 0) {
        const float* b = Wk_b + l * D;
        float s = 0.f;
        for (int o = 0; o < D; o++) s += re[o] * b[o];
        rb[l * NR + rr] = s;
    }
    if (blockIdx.x == 0 && d == 0) *acc = 0.f;
}

// ---------------- transpose gate weights once: wt[l][d][o] = W[l][o][d] ----
__global__ void k_prep(const float* __restrict__ Wa_w,
                       const float* __restrict__ Wa_b,
                       const float* __restrict__ Wb_w,
                       const float* __restrict__ Wb_b,
                       float* __restrict__ wat, float* __restrict__ wbt,
                       float* __restrict__ bsum) {
    int i = blockIdx.x * 256 + threadIdx.x;
    if (i >= LAYERS * D * D) return;
    int l = i >> 12, r = i & 4095, dd = r >> 6, o = r & 63;
    wat[i] = Wa_w[l * D * D + o * D + dd];
    wbt[i] = Wb_w[l * D * D + o * D + dd];
    if (r < D) bsum[l * D + r] = Wa_b[l * D + r] + Wb_b[l * D + r];
}

// ---------------- KG attention: one warp per item (rw read via L1) ---------
__global__ void k_attn(const float* __restrict__ icur,
                       const float* __restrict__ eemb,
                       const int* __restrict__ kg_ent,
                       const int* __restrict__ kg_rel,
                       const float* __restrict__ rw,
                       const float* __restrict__ rb,
                       float* __restrict__ kg_out) {
    int tid = threadIdx.x;
    int warp = tid >> 5, lane = tid & 31;
    int item = blockIdx.x * 8 + warp;
    if (item >= NI) return;

    float2 ic = *(const float2*)(icur + (size_t)item * D + lane * 2);
    float2 v[KNB];
    float sc[KNB];
    int base = item * KNB;
#pragma unroll
    for (int k = 0; k < KNB; k++) {
        int e = __ldg(&kg_ent[base + k]);
        int rr = __ldg(&kg_rel[base + k]);
        v[k] = *(const float2*)(eemb + (size_t)e * D + lane * 2);
        float2 w = *(const float2*)(rw + rr * D + lane * 2);
        float p = v[k].x * ic.x * w.x + v[k].y * ic.y * w.y;
#pragma unroll
        for (int off = 16; off; off >>= 1) p += __shfl_xor_sync(0xffffffffu, p, off);
        p += __ldg(&rb[rr]);
        sc[k] = p >= 0.f ? p : 0.2f * p;
    }
    float m = sc[0];
#pragma unroll
    for (int k = 1; k < KNB; k++) m = fmaxf(m, sc[k]);
    float s = 0.f;
#pragma unroll
    for (int k = 0; k < KNB; k++) { sc[k] = __expf(sc[k] - m); s += sc[k]; }
    float inv = 1.f / s;
    float ax = 0.f, ay = 0.f;
#pragma unroll
    for (int k = 0; k < KNB; k++) {
        float a = sc[k] * inv;
        ax += a * v[k].x;
        ay += a * v[k].y;
    }
    float2 o;
    o.x = ax; o.y = ay;
    *(float2*)(kg_out + (size_t)item * D + lane * 2) = o;
}

// ---------------- edge scatter: one warp per edge ---------------------------
__global__ void k_scatter(const float* __restrict__ ucur,
                          const float* __restrict__ icur,
                          const int* __restrict__ eu,
                          const int* __restrict__ ei,
                          const float* __restrict__ enorm,
                          float* __restrict__ aggu,
                          float* __restrict__ aggi) {
    int e = (blockIdx.x * blockDim.x + threadIdx.x) >> 5;
    int lane = threadIdx.x & 31;
    if (e >= EDGES) return;
    int u = eu[e];
    int i = ei[e];
    float nrm = enorm[e];
    int part = lane >> 4;
    int j = (lane & 15) * 4;
    const float* src = part ? icur + (size_t)i * D + j : ucur + (size_t)u * D + j;
    float* dst = part ? aggu + (size_t)u * D + j : aggi + (size_t)i * D + j;
    float4 s = *(const float4*)src;
    asm volatile("red.global.add.v4.f32 [%0], {%1,%2,%3,%4};"
                 :: "l"(dst), "f"(nrm * s.x), "f"(nrm * s.y),
                    "f"(nrm * s.z), "f"(nrm * s.w)
                 : "memory");
}

// ---------------- gate + item update ----------------------------------------
// block = 256 threads, 64 items; warp handles 8 items, lane owns outputs
// (2*lane, 2*lane+1). Weights pre-transposed [d][o], padded stride 66 in smem.
#define G_ITEMS 64
#define G_PITCH 66
__global__ void k_gate(const float* __restrict__ kg,
                       const float* __restrict__ aggi,
                       const float* __restrict__ wat,
                       const float* __restrict__ wbt,
                       const float* __restrict__ bsum,
                       float* __restrict__ inew) {
    extern __shared__ float sm[];
    float* sWa = sm;                       // 64*66
    float* sWb = sWa + D * G_PITCH;        // 64*66
    float* skg = sWb + D * G_PITCH;        // 64*64
    float* sag = skg + G_ITEMS * D;        // 64*64
    float* sb  = sag + G_ITEMS * D;        // 64

    int tid = threadIdx.x;
    int base = blockIdx.x * G_ITEMS;

    // stage transposed weights: coalesced LDG, conflict-free STS
    for (int i = tid; i < D * D; i += 256) {
        int dd = i >> 6, o = i & 63;
        sWa[dd * G_PITCH + o] = wat[i];
        sWb[dd * G_PITCH + o] = wbt[i];
    }
    if (tid < D) sb[tid] = bsum[tid];

    // stage x (kg and aggi rows), float4 coalesced
    for (int i = tid; i < G_ITEMS * (D / 4); i += 256) {
        int it = i >> 4, c = i & 15;
        int gidx = base + it; if (gidx >= NI) gidx = NI - 1;
        ((float4*)skg)[it * 16 + c] = ((const float4*)kg)[(size_t)gidx * 16 + c];
        ((float4*)sag)[it * 16 + c] = ((const float4*)aggi)[(size_t)gidx * 16 + c];
    }
    __syncthreads();

    int warp = tid >> 5, lane = tid & 31;
    float2 acc[8];
#pragma unroll
    for (int j = 0; j < 8; j++) { acc[j].x = 0.f; acc[j].y = 0.f; }

    for (int d = 0; d < D; d += 2) {
        float2 wa0 = *(const float2*)(sWa + d * G_PITCH + 2 * lane);
        float2 wa1 = *(const float2*)(sWa + (d + 1) * G_PITCH + 2 * lane);
        float2 wb0 = *(const float2*)(sWb + d * G_PITCH + 2 * lane);
        float2 wb1 = *(const float2*)(sWb + (d + 1) * G_PITCH + 2 * lane);
#pragma unroll
        for (int j = 0; j < 8; j++) {
            int it = warp * 8 + j;
            float2 xk = *(const float2*)(skg + it * D + d);   // broadcast
            float2 xa = *(const float2*)(sag + it * D + d);   // broadcast
            acc[j].x += xk.x * wa0.x + xk.y * wa1.x + xa.x * wb0.x + xa.y * wb1.x;
            acc[j].y += xk.x * wa0.y + xk.y * wa1.y + xa.x * wb0.y + xa.y * wb1.y;
        }
    }

    float2 b2 = *(const float2*)(sb + 2 * lane);
#pragma unroll
    for (int j = 0; j < 8; j++) {
        int it = warp * 8 + j;
        if (base + it >= NI) break;
        float gx = 1.f / (1.f + __expf(-(acc[j].x + b2.x)));
        float gy = 1.f / (1.f + __expf(-(acc[j].y + b2.y)));
        float2 kv = *(const float2*)(skg + it * D + 2 * lane);
        float2 av = *(const float2*)(sag + it * D + 2 * lane);
        float2 o2;
        o2.x = gx * kv.x + (1.f - gx) * av.x;
        o2.y = gy * kv.y + (1.f - gy) * av.y;
        ((float2*)(inew + (size_t)(base + it) * D))[lane] = o2;
    }
}
#define G_SMEM ((2 * D * G_PITCH + 2 * G_ITEMS * D + D) * sizeof(float))

// ---------------- loss: one warp per batch element --------------------------
__global__ void k_loss(const float* __restrict__ uemb,
                       const float* __restrict__ aggu0,
                       const float* __restrict__ aggu1,
                       const float* __restrict__ iemb,
                       const float* __restrict__ ic1,
                       const float* __restrict__ ic2,
                       const int* __restrict__ user,
                       const int* __restrict__ pos,
                       const int* __restrict__ neg,
                       float* __restrict__ acc) {
    int b = (blockIdx.x * blockDim.x + threadIdx.x) >> 5;
    int lane = threadIdx.x & 31;
    if (b >= BB) return;
    size_t u = (size_t)user[b] * D;
    size_t p = (size_t)pos[b] * D;
    size_t n = (size_t)neg[b] * D;

    int d = lane * 2;
    float2 ua = *(const float2*)(uemb + u + d);
    float2 ub = *(const float2*)(aggu0 + u + d);
    float2 uc = *(const float2*)(aggu1 + u + d);
    float2 pa = *(const float2*)(iemb + p + d);
    float2 pb = *(const float2*)(ic1 + p + d);
    float2 pc = *(const float2*)(ic2 + p + d);
    float2 na = *(const float2*)(iemb + n + d);
    float2 nb = *(const float2*)(ic1 + n + d);
    float2 nc = *(const float2*)(ic2 + n + d);
    float uex = ua.x + ub.x + uc.x, uey = ua.y + ub.y + uc.y;
    float pex = pa.x + pb.x + pc.x, pey = pa.y + pb.y + pc.y;
    float nex = na.x + nb.x + nc.x, ney = na.y + nb.y + nc.y;
    float ps = uex * pex + uey * pey;
    float ns = uex * nex + uey * ney;
    float l2 = uex * uex + uey * uey + pex * pex + pey * pey + nex * nex + ney * ney;
#pragma unroll
    for (int off = 16; off; off >>= 1) {
        ps += __shfl_xor_sync(0xffffffffu, ps, off);
        ns += __shfl_xor_sync(0xffffffffu, ns, off);
        l2 += __shfl_xor_sync(0xffffffffu, l2, off);
    }
    if (lane == 0) {
        float x = ps - ns;
        float sg = 1.f / (1.f + expf(-x));
        float term = -logf(sg + 1e-10f) + REG * l2;
        atomicAdd(acc, term);
    }
}

__global__ void k_final(const float* __restrict__ acc, float* __restrict__ out) {
    out[0] = acc[0] * (1.f / (float)BB);
}

// ---------------- launch -----------------------------------------------------
extern "C" void kernel_launch(void* const* d_in, const int* in_sizes, int n_in,
                              void* d_out, int out_size) {
    const float* uemb  = (const float*)d_in[0];
    const float* iemb  = (const float*)d_in[1];
    const float* eemb  = (const float*)d_in[2];
    const float* remb  = (const float*)d_in[3];
    const float* Wk_w  = (const float*)d_in[4];
    const float* Wk_b  = (const float*)d_in[5];
    const float* Wa_w  = (const float*)d_in[6];
    const float* Wa_b  = (const float*)d_in[7];
    const float* Wb_w  = (const float*)d_in[8];
    const float* Wb_b  = (const float*)d_in[9];
    const float* enorm = (const float*)d_in[10];
    const int* user    = (const int*)d_in[11];
    const int* pos     = (const int*)d_in[12];
    const int* neg     = (const int*)d_in[13];
    const int* eu      = (const int*)d_in[14];
    const int* ei      = (const int*)d_in[15];
    const int* kg_rel  = (const int*)d_in[16];
    const int* kg_ent  = (const int*)d_in[17];

    float *agg, *kg, *ic1, *ic2, *rw, *rb, *wat, *wbt, *bsum, *acc;
    cudaGetSymbolAddress((void**)&agg, g_agg);
    cudaGetSymbolAddress((void**)&kg, g_kg);
    cudaGetSymbolAddress((void**)&ic1, g_ic1);
    cudaGetSymbolAddress((void**)&ic2, g_ic2);
    cudaGetSymbolAddress((void**)&rw, g_rw);
    cudaGetSymbolAddress((void**)&rb, g_rb);
    cudaGetSymbolAddress((void**)&wat, g_wat);
    cudaGetSymbolAddress((void**)&wbt, g_wbt);
    cudaGetSymbolAddress((void**)&bsum, g_bsum);
    cudaGetSymbolAddress((void**)&acc, g_acc);

    float* aggu0 = agg;
    float* aggu1 = agg + (size_t)NU * D;
    float* aggi0 = agg + (size_t)2 * NU * D;
    float* aggi1 = agg + (size_t)2 * NU * D + (size_t)NI * D;

    static int smem_set = 0;
    if (!smem_set) {
        cudaFuncSetAttribute(k_gate, cudaFuncAttributeMaxDynamicSharedMemorySize,
                             (int)G_SMEM);
        smem_set = 1;
    }

    cudaMemsetAsync(agg, 0, sizeof(float) * (size_t)(2 * NU + 2 * NI) * D);

    k_rw<<<LAYERS * NR, D>>>(remb, Wk_w, Wk_b, rw, rb, acc);
    k_prep<<<(LAYERS * D * D + 255) / 256, 256>>>(Wa_w, Wa_b, Wb_w, Wb_b,
                                                  wat, wbt, bsum);

    // ---- layer 0 (u_cur = uemb, i_cur = iemb) ----
    k_attn<<<(NI + 7) / 8, 256>>>(iemb, eemb, kg_ent, kg_rel, rw, rb, kg);
    k_scatter<<<(EDGES * 32 + 255) / 256, 256>>>(uemb, iemb, eu, ei, enorm, aggu0, aggi0);
    k_gate<<<(NI + G_ITEMS - 1) / G_ITEMS, 256, G_SMEM>>>(kg, aggi0, wat, wbt, bsum, ic1);

    // ---- layer 1 (u_cur = aggu0, i_cur = ic1) ----
    k_attn<<<(NI + 7) / 8, 256>>>(ic1, eemb, kg_ent, kg_rel, rw + NR * D, rb + NR, kg);
    k_scatter<<<(EDGES * 32 + 255) / 256, 256>>>(aggu0, ic1, eu, ei, enorm, aggu1, aggi1);
    k_gate<<<(NI + G_ITEMS - 1) / G_ITEMS, 256, G_SMEM>>>(kg, aggi1,
                                                          wat + D * D, wbt + D * D,
                                                          bsum + D, ic2);

    // ---- loss ----
    k_loss<<<(BB * 32 + 255) / 256, 256>>>(uemb, aggu0, aggu1, iemb, ic1, ic2,
                                           user, pos, neg, acc);
    k_final<<<1, 1>>>(acc, (float*)d_out);
}

// round 3
// speedup vs baseline: 1.7742x; 1.5254x over previous
#include <cuda_runtime.h>
#include <cuda_bf16.h>

#define NU 100000
#define NI 50000
#define NE 200000
#define NR 64
#define D 64
#define KNB 16
#define EDGES 2000000
#define LAYERS 2
#define BB 4096
#define REG 0.0001f
#define NSEG (NI + NU)   // CSR segments: items first, then users

// ---------------- scratch (no alloc allowed -> __device__ globals) ----------
__device__ float g_agg[(2 * NU + 2 * NI) * D];
__device__ float g_kg[NI * D];
__device__ float g_ic1[NI * D];
__device__ float g_ic2[NI * D];
__device__ float g_rw[LAYERS * NR * D];
__device__ float g_rb[LAYERS * NR];
__device__ float g_wat[LAYERS * D * D];
__device__ float g_wbt[LAYERS * D * D];
__device__ float g_bsum[LAYERS * D];
__device__ float g_acc;
// CSR scratch
__device__ int   g_cnt[NSEG];          // histogram, then reused as fill cursor
__device__ int   g_off[NSEG + 1];      // exclusive offsets
__device__ int   g_bs[256];            // block sums for scan
__device__ int2  g_csr[2 * EDGES];     // (src_idx, norm-bits) sorted by dst

// ---------------- rw[l,rel,d] = sum_o r_o * (Wk[:, :D]+Wk[:, D:])[o,d] ------
__global__ void k_rw(const float* __restrict__ remb,
                     const float* __restrict__ Wk_w,
                     const float* __restrict__ Wk_b,
                     float* __restrict__ rw, float* __restrict__ rb,
                     float* __restrict__ acc) {
    int l = blockIdx.x >> 6;
    int rr = blockIdx.x & 63;
    int d = threadIdx.x;
    const float* W = Wk_w + (size_t)l * D * 2 * D;
    const float* re = remb + rr * D;
    float a = 0.f;
#pragma unroll 8
    for (int o = 0; o < D; o++)
        a += re[o] * (W[o * 2 * D + d] + W[o * 2 * D + D + d]);
    rw[(l * NR + rr) * D + d] = a;
    if (d == 0) {
        const float* b = Wk_b + l * D;
        float s = 0.f;
        for (int o = 0; o < D; o++) s += re[o] * b[o];
        rb[l * NR + rr] = s;
    }
    if (blockIdx.x == 0 && d == 0) *acc = 0.f;
}

// ---------------- transpose gate weights once -------------------------------
__global__ void k_prep(const float* __restrict__ Wa_w,
                       const float* __restrict__ Wa_b,
                       const float* __restrict__ Wb_w,
                       const float* __restrict__ Wb_b,
                       float* __restrict__ wat, float* __restrict__ wbt,
                       float* __restrict__ bsum) {
    int i = blockIdx.x * 256 + threadIdx.x;
    if (i >= LAYERS * D * D) return;
    int l = i >> 12, r = i & 4095, dd = r >> 6, o = r & 63;
    wat[i] = Wa_w[l * D * D + o * D + dd];
    wbt[i] = Wb_w[l * D * D + o * D + dd];
    if (r < D) bsum[l * D + r] = Wa_b[l * D + r] + Wb_b[l * D + r];
}

// ---------------- CSR build --------------------------------------------------
__global__ void k_hist(const int* __restrict__ eu, const int* __restrict__ ei,
                       int* __restrict__ cnt) {
    int e = blockIdx.x * 256 + threadIdx.x;
    if (e >= EDGES) return;
    atomicAdd(&cnt[ei[e]], 1);
    atomicAdd(&cnt[NI + eu[e]], 1);
}

__global__ void k_scan1(const int* __restrict__ cnt, int* __restrict__ off,
                        int* __restrict__ bs) {
    __shared__ int sh[1024];
    int gid = blockIdx.x * 1024 + threadIdx.x;
    int v = gid < NSEG ? cnt[gid] : 0;
    sh[threadIdx.x] = v;
    __syncthreads();
#pragma unroll
    for (int d = 1; d < 1024; d <<= 1) {
        int t = threadIdx.x >= d ? sh[threadIdx.x - d] : 0;
        __syncthreads();
        sh[threadIdx.x] += t;
        __syncthreads();
    }
    if (gid < NSEG) off[gid] = sh[threadIdx.x] - v;   // exclusive
    if (threadIdx.x == 1023) bs[blockIdx.x] = sh[1023];
}

__global__ void k_scan2(int* __restrict__ bs, int nb) {
    __shared__ int sh[256];
    int v = (int)threadIdx.x < nb ? bs[threadIdx.x] : 0;
    sh[threadIdx.x] = v;
    __syncthreads();
#pragma unroll
    for (int d = 1; d < 256; d <<= 1) {
        int t = threadIdx.x >= d ? sh[threadIdx.x - d] : 0;
        __syncthreads();
        sh[threadIdx.x] += t;
        __syncthreads();
    }
    if ((int)threadIdx.x < nb) bs[threadIdx.x] = sh[threadIdx.x] - v;
}

__global__ void k_scan3(int* __restrict__ off, const int* __restrict__ bs) {
    int gid = blockIdx.x * 1024 + threadIdx.x;
    if (gid < NSEG) off[gid] += bs[blockIdx.x];
    if (gid == 0) off[NSEG] = 2 * EDGES;
}

__global__ void k_fill(const int* __restrict__ eu, const int* __restrict__ ei,
                       const float* __restrict__ enorm,
                       const int* __restrict__ off, int* __restrict__ cur,
                       int2* __restrict__ csr) {
    int e = blockIdx.x * 256 + threadIdx.x;
    if (e >= EDGES) return;
    int u = eu[e], i = ei[e];
    int nb = __float_as_int(enorm[e]);
    int p1 = off[i] + atomicAdd(&cur[i], 1);
    int2 a; a.x = u; a.y = nb;
    csr[p1] = a;
    int p2 = off[NI + u] + atomicAdd(&cur[NI + u], 1);
    int2 b; b.x = i; b.y = nb;
    csr[p2] = b;
}

// ---------------- segmented gather-sum: one warp per destination row --------
// segments [0,NI): aggi[w] = sum nrm * ucur[src];  [NI,NSEG): aggu = sum nrm*icur
__global__ void k_gather(const float* __restrict__ ucur,
                         const float* __restrict__ icur,
                         const int2* __restrict__ csr,
                         const int* __restrict__ off,
                         float* __restrict__ aggu,
                         float* __restrict__ aggi) {
    int w = (blockIdx.x * blockDim.x + threadIdx.x) >> 5;
    int lane = threadIdx.x & 31;
    if (w >= NSEG) return;
    const float* src = w < NI ? ucur : icur;
    float* out = w < NI ? aggi + (size_t)w * D : aggu + (size_t)(w - NI) * D;
    int s = off[w], e = off[w + 1];
    int g = lane >> 4;          // half-warp group: edges s+g, s+g+2, ...
    int j = (lane & 15) * 4;    // 16B chunk of the row
    float4 acc = make_float4(0.f, 0.f, 0.f, 0.f);
    for (int t = s + g; t < e; t += 2) {
        int2 pr = __ldg(&csr[t]);
        float nrm = __int_as_float(pr.y);
        float4 v = *(const float4*)(src + (size_t)pr.x * D + j);
        acc.x += nrm * v.x; acc.y += nrm * v.y;
        acc.z += nrm * v.z; acc.w += nrm * v.w;
    }
    acc.x += __shfl_xor_sync(0xffffffffu, acc.x, 16);
    acc.y += __shfl_xor_sync(0xffffffffu, acc.y, 16);
    acc.z += __shfl_xor_sync(0xffffffffu, acc.z, 16);
    acc.w += __shfl_xor_sync(0xffffffffu, acc.w, 16);
    if (g == 0) *(float4*)(out + j) = acc;
}

// ---------------- KG attention: one warp per item ---------------------------
__global__ void k_attn(const float* __restrict__ icur,
                       const float* __restrict__ eemb,
                       const int* __restrict__ kg_ent,
                       const int* __restrict__ kg_rel,
                       const float* __restrict__ rw,
                       const float* __restrict__ rb,
                       float* __restrict__ kg_out) {
    int tid = threadIdx.x;
    int warp = tid >> 5, lane = tid & 31;
    int item = blockIdx.x * 8 + warp;
    if (item >= NI) return;

    float2 ic = *(const float2*)(icur + (size_t)item * D + lane * 2);
    float2 v[KNB];
    float sc[KNB];
    int base = item * KNB;
#pragma unroll
    for (int k = 0; k < KNB; k++) {
        int e = __ldg(&kg_ent[base + k]);
        int rr = __ldg(&kg_rel[base + k]);
        v[k] = *(const float2*)(eemb + (size_t)e * D + lane * 2);
        float2 w = *(const float2*)(rw + rr * D + lane * 2);
        float p = v[k].x * ic.x * w.x + v[k].y * ic.y * w.y;
#pragma unroll
        for (int off = 16; off; off >>= 1) p += __shfl_xor_sync(0xffffffffu, p, off);
        p += __ldg(&rb[rr]);
        sc[k] = p >= 0.f ? p : 0.2f * p;
    }
    float m = sc[0];
#pragma unroll
    for (int k = 1; k < KNB; k++) m = fmaxf(m, sc[k]);
    float s = 0.f;
#pragma unroll
    for (int k = 0; k < KNB; k++) { sc[k] = __expf(sc[k] - m); s += sc[k]; }
    float inv = 1.f / s;
    float ax = 0.f, ay = 0.f;
#pragma unroll
    for (int k = 0; k < KNB; k++) {
        float a = sc[k] * inv;
        ax += a * v[k].x;
        ay += a * v[k].y;
    }
    float2 o;
    o.x = ax; o.y = ay;
    *(float2*)(kg_out + (size_t)item * D + lane * 2) = o;
}

// ---------------- gate + item update ----------------------------------------
#define G_ITEMS 64
#define G_PITCH 66
__global__ void k_gate(const float* __restrict__ kg,
                       const float* __restrict__ aggi,
                       const float* __restrict__ wat,
                       const float* __restrict__ wbt,
                       const float* __restrict__ bsum,
                       float* __restrict__ inew) {
    extern __shared__ float sm[];
    float* sWa = sm;
    float* sWb = sWa + D * G_PITCH;
    float* skg = sWb + D * G_PITCH;
    float* sag = skg + G_ITEMS * D;
    float* sb  = sag + G_ITEMS * D;

    int tid = threadIdx.x;
    int base = blockIdx.x * G_ITEMS;

    for (int i = tid; i < D * D; i += 256) {
        int dd = i >> 6, o = i & 63;
        sWa[dd * G_PITCH + o] = wat[i];
        sWb[dd * G_PITCH + o] = wbt[i];
    }
    if (tid < D) sb[tid] = bsum[tid];

    for (int i = tid; i < G_ITEMS * (D / 4); i += 256) {
        int it = i >> 4, c = i & 15;
        int gidx = base + it; if (gidx >= NI) gidx = NI - 1;
        ((float4*)skg)[it * 16 + c] = ((const float4*)kg)[(size_t)gidx * 16 + c];
        ((float4*)sag)[it * 16 + c] = ((const float4*)aggi)[(size_t)gidx * 16 + c];
    }
    __syncthreads();

    int warp = tid >> 5, lane = tid & 31;
    float2 acc[8];
#pragma unroll
    for (int j = 0; j < 8; j++) { acc[j].x = 0.f; acc[j].y = 0.f; }

    for (int d = 0; d < D; d += 2) {
        float2 wa0 = *(const float2*)(sWa + d * G_PITCH + 2 * lane);
        float2 wa1 = *(const float2*)(sWa + (d + 1) * G_PITCH + 2 * lane);
        float2 wb0 = *(const float2*)(sWb + d * G_PITCH + 2 * lane);
        float2 wb1 = *(const float2*)(sWb + (d + 1) * G_PITCH + 2 * lane);
#pragma unroll
        for (int j = 0; j < 8; j++) {
            int it = warp * 8 + j;
            float2 xk = *(const float2*)(skg + it * D + d);
            float2 xa = *(const float2*)(sag + it * D + d);
            acc[j].x += xk.x * wa0.x + xk.y * wa1.x + xa.x * wb0.x + xa.y * wb1.x;
            acc[j].y += xk.x * wa0.y + xk.y * wa1.y + xa.x * wb0.y + xa.y * wb1.y;
        }
    }

    float2 b2 = *(const float2*)(sb + 2 * lane);
#pragma unroll
    for (int j = 0; j < 8; j++) {
        int it = warp * 8 + j;
        if (base + it >= NI) break;
        float gx = 1.f / (1.f + __expf(-(acc[j].x + b2.x)));
        float gy = 1.f / (1.f + __expf(-(acc[j].y + b2.y)));
        float2 kv = *(const float2*)(skg + it * D + 2 * lane);
        float2 av = *(const float2*)(sag + it * D + 2 * lane);
        float2 o2;
        o2.x = gx * kv.x + (1.f - gx) * av.x;
        o2.y = gy * kv.y + (1.f - gy) * av.y;
        ((float2*)(inew + (size_t)(base + it) * D))[lane] = o2;
    }
}
#define G_SMEM ((2 * D * G_PITCH + 2 * G_ITEMS * D + D) * sizeof(float))

// ---------------- loss -------------------------------------------------------
__global__ void k_loss(const float* __restrict__ uemb,
                       const float* __restrict__ aggu0,
                       const float* __restrict__ aggu1,
                       const float* __restrict__ iemb,
                       const float* __restrict__ ic1,
                       const float* __restrict__ ic2,
                       const int* __restrict__ user,
                       const int* __restrict__ pos,
                       const int* __restrict__ neg,
                       float* __restrict__ acc) {
    int b = (blockIdx.x * blockDim.x + threadIdx.x) >> 5;
    int lane = threadIdx.x & 31;
    if (b >= BB) return;
    size_t u = (size_t)user[b] * D;
    size_t p = (size_t)pos[b] * D;
    size_t n = (size_t)neg[b] * D;

    int d = lane * 2;
    float2 ua = *(const float2*)(uemb + u + d);
    float2 ub = *(const float2*)(aggu0 + u + d);
    float2 uc = *(const float2*)(aggu1 + u + d);
    float2 pa = *(const float2*)(iemb + p + d);
    float2 pb = *(const float2*)(ic1 + p + d);
    float2 pc = *(const float2*)(ic2 + p + d);
    float2 na = *(const float2*)(iemb + n + d);
    float2 nb = *(const float2*)(ic1 + n + d);
    float2 nc = *(const float2*)(ic2 + n + d);
    float uex = ua.x + ub.x + uc.x, uey = ua.y + ub.y + uc.y;
    float pex = pa.x + pb.x + pc.x, pey = pa.y + pb.y + pc.y;
    float nex = na.x + nb.x + nc.x, ney = na.y + nb.y + nc.y;
    float ps = uex * pex + uey * pey;
    float ns = uex * nex + uey * ney;
    float l2 = uex * uex + uey * uey + pex * pex + pey * pey + nex * nex + ney * ney;
#pragma unroll
    for (int off = 16; off; off >>= 1) {
        ps += __shfl_xor_sync(0xffffffffu, ps, off);
        ns += __shfl_xor_sync(0xffffffffu, ns, off);
        l2 += __shfl_xor_sync(0xffffffffu, l2, off);
    }
    if (lane == 0) {
        float x = ps - ns;
        float sg = 1.f / (1.f + expf(-x));
        float term = -logf(sg + 1e-10f) + REG * l2;
        atomicAdd(acc, term);
    }
}

__global__ void k_final(const float* __restrict__ acc, float* __restrict__ out) {
    out[0] = acc[0] * (1.f / (float)BB);
}

// ---------------- launch -----------------------------------------------------
extern "C" void kernel_launch(void* const* d_in, const int* in_sizes, int n_in,
                              void* d_out, int out_size) {
    const float* uemb  = (const float*)d_in[0];
    const float* iemb  = (const float*)d_in[1];
    const float* eemb  = (const float*)d_in[2];
    const float* remb  = (const float*)d_in[3];
    const float* Wk_w  = (const float*)d_in[4];
    const float* Wk_b  = (const float*)d_in[5];
    const float* Wa_w  = (const float*)d_in[6];
    const float* Wa_b  = (const float*)d_in[7];
    const float* Wb_w  = (const float*)d_in[8];
    const float* Wb_b  = (const float*)d_in[9];
    const float* enorm = (const float*)d_in[10];
    const int* user    = (const int*)d_in[11];
    const int* pos     = (const int*)d_in[12];
    const int* neg     = (const int*)d_in[13];
    const int* eu      = (const int*)d_in[14];
    const int* ei      = (const int*)d_in[15];
    const int* kg_rel  = (const int*)d_in[16];
    const int* kg_ent  = (const int*)d_in[17];

    float *agg, *kg, *ic1, *ic2, *rw, *rb, *wat, *wbt, *bsum, *acc;
    int *cnt, *off, *bs;
    int2 *csr;
    cudaGetSymbolAddress((void**)&agg, g_agg);
    cudaGetSymbolAddress((void**)&kg, g_kg);
    cudaGetSymbolAddress((void**)&ic1, g_ic1);
    cudaGetSymbolAddress((void**)&ic2, g_ic2);
    cudaGetSymbolAddress((void**)&rw, g_rw);
    cudaGetSymbolAddress((void**)&rb, g_rb);
    cudaGetSymbolAddress((void**)&wat, g_wat);
    cudaGetSymbolAddress((void**)&wbt, g_wbt);
    cudaGetSymbolAddress((void**)&bsum, g_bsum);
    cudaGetSymbolAddress((void**)&acc, g_acc);
    cudaGetSymbolAddress((void**)&cnt, g_cnt);
    cudaGetSymbolAddress((void**)&off, g_off);
    cudaGetSymbolAddress((void**)&bs, g_bs);
    cudaGetSymbolAddress((void**)&csr, g_csr);

    float* aggu0 = agg;
    float* aggu1 = agg + (size_t)NU * D;
    float* aggi0 = agg + (size_t)2 * NU * D;
    float* aggi1 = agg + (size_t)2 * NU * D + (size_t)NI * D;

    cudaFuncSetAttribute(k_gate, cudaFuncAttributeMaxDynamicSharedMemorySize,
                         (int)G_SMEM);

    const int SCAN_BLOCKS = (NSEG + 1023) / 1024;

    // ---- CSR build (edge structure shared by both layers) ----
    cudaMemsetAsync(cnt, 0, sizeof(int) * NSEG);
    k_hist<<<(EDGES + 255) / 256, 256>>>(eu, ei, cnt);
    k_scan1<<<SCAN_BLOCKS, 1024>>>(cnt, off, bs);
    k_scan2<<<1, 256>>>(bs, SCAN_BLOCKS);
    k_scan3<<<SCAN_BLOCKS, 1024>>>(off, bs);
    cudaMemsetAsync(cnt, 0, sizeof(int) * NSEG);   // reuse as fill cursor
    k_fill<<<(EDGES + 255) / 256, 256>>>(eu, ei, enorm, off, cnt, csr);

    // ---- weight precompute ----
    k_rw<<<LAYERS * NR, D>>>(remb, Wk_w, Wk_b, rw, rb, acc);
    k_prep<<<(LAYERS * D * D + 255) / 256, 256>>>(Wa_w, Wa_b, Wb_w, Wb_b,
                                                  wat, wbt, bsum);

    const int GATHER_BLOCKS = (NSEG + 7) / 8;

    // ---- layer 0 (u_cur = uemb, i_cur = iemb) ----
    k_attn<<<(NI + 7) / 8, 256>>>(iemb, eemb, kg_ent, kg_rel, rw, rb, kg);
    k_gather<<<GATHER_BLOCKS, 256>>>(uemb, iemb, csr, off, aggu0, aggi0);
    k_gate<<<(NI + G_ITEMS - 1) / G_ITEMS, 256, G_SMEM>>>(kg, aggi0, wat, wbt, bsum, ic1);

    // ---- layer 1 (u_cur = aggu0, i_cur = ic1) ----
    k_attn<<<(NI + 7) / 8, 256>>>(ic1, eemb, kg_ent, kg_rel, rw + NR * D, rb + NR, kg);
    k_gather<<<GATHER_BLOCKS, 256>>>(aggu0, ic1, csr, off, aggu1, aggi1);
    k_gate<<<(NI + G_ITEMS - 1) / G_ITEMS, 256, G_SMEM>>>(kg, aggi1,
                                                          wat + D * D, wbt + D * D,
                                                          bsum + D, ic2);

    // ---- loss ----
    k_loss<<<(BB * 32 + 255) / 256, 256>>>(uemb, aggu0, aggu1, iemb, ic1, ic2,
                                           user, pos, neg, acc);
    k_final<<<1, 1>>>(acc, (float*)d_out);
}